// round 8
// baseline (speedup 1.0000x reference)
#include <cuda_runtime.h>

#define NB   4
#define NN   50000
#define FIN  32
#define H2   30
#define BN   (NB*NN)       // 200000 node-batch rows
#define BD   128           // gather-kernel block size
#define PB   256           // proj/out block size
#define IG   1024          // init grid
#define EMAX 800000

typedef unsigned long long ull;

// Static scratch (no allocations allowed).
__device__ __align__(128) float g_YA[(size_t)BN*32];   // x @ W1[0:32]
__device__ __align__(128) float g_YB[(size_t)BN*32];   // x @ W1[32:64] + b1
__device__ __align__(128) float g_SC[(size_t)BN*32];   // padded 30->32 accumulator
__device__ int g_hist[NN];
__device__ int g_cur[NN];
__device__ unsigned g_arrA[2*EMAX];   // edge | sign<<31
__device__ unsigned g_arrB[2*EMAX];   // node | other<<16
__device__ double g_sum, g_sumsq;
__device__ float  g_mean, g_istd;
__device__ int    g_is64;
__device__ unsigned g_ticket;

union F4U2 { float4 f4; ull u[2]; float f[4]; };
union F2U1 { float2 f2; ull u; float f[2]; };

__device__ __forceinline__ float sigmoidf(float x){          // final layer
    return __fdividef(1.0f, 1.0f + __expf(-x));
}
__device__ __forceinline__ float sigm_fast(float x){         // hidden layers
    float t;
    asm("tanh.approx.f32 %0, %1;" : "=f"(t) : "f"(x * 0.5f));
    return fmaf(t, 0.5f, 0.5f);
}
__device__ __forceinline__ ull pack2(float lo, float hi){
    ull r; asm("mov.b64 %0, {%1,%2};" : "=l"(r) : "f"(lo), "f"(hi)); return r;
}
#define FMA2(acc, a, b) asm("fma.rn.f32x2 %0, %1, %2, %0;" : "+l"(acc) : "l"(a), "l"(b))
#define ADD2(d, a, b)   asm("add.rn.f32x2 %0, %1, %2;"     : "=l"(d)  : "l"(a), "l"(b))

__device__ __forceinline__ void red_add_f(float* p, float v){
    asm volatile("red.global.add.f32 [%0], %1;" :: "l"(p), "f"(v) : "memory");
}

// ---------------- K0: zero SC + hist, edge_attr stats, dtype probe, finalize ----------------
__global__ void k_init(const int* __restrict__ ei32, const float* __restrict__ ea, int E){
    size_t n4 = (size_t)BN*32/4;
    float4 z = make_float4(0.f,0.f,0.f,0.f);
    float4* p = (float4*)g_SC;
    size_t g0 = (size_t)blockIdx.x*blockDim.x + threadIdx.x;
    size_t gs = (size_t)gridDim.x*blockDim.x;
    for (size_t i = g0; i < n4; i += gs) p[i] = z;
    for (size_t i = g0; i < NN; i += gs) g_hist[i] = 0;

    if (blockIdx.x==0 && threadIdx.x==0){
        int all_hi_zero = 1;
        for (int k = 1; k < 512; k += 2) all_hi_zero &= (ei32[k] == 0);
        g_is64 = all_hi_zero;
    }

    float s = 0.f, s2 = 0.f;
    for (int i = blockIdx.x*blockDim.x + threadIdx.x; i < E; i += gridDim.x*blockDim.x){
        float v = ea[i]; s += v; s2 = fmaf(v, v, s2);
    }
    #pragma unroll
    for (int o = 16; o; o >>= 1){
        s  += __shfl_down_sync(0xffffffffu, s,  o);
        s2 += __shfl_down_sync(0xffffffffu, s2, o);
    }
    __shared__ float ws[32], ws2[32];
    __shared__ int last;
    int lane = threadIdx.x & 31, w = threadIdx.x >> 5;
    if (lane == 0){ ws[w] = s; ws2[w] = s2; }
    __syncthreads();
    if (w == 0){
        int nw = blockDim.x >> 5;
        s  = (lane < nw) ? ws[lane]  : 0.f;
        s2 = (lane < nw) ? ws2[lane] : 0.f;
        #pragma unroll
        for (int o = 16; o; o >>= 1){
            s  += __shfl_down_sync(0xffffffffu, s,  o);
            s2 += __shfl_down_sync(0xffffffffu, s2, o);
        }
        if (lane == 0){ atomicAdd(&g_sum, (double)s); atomicAdd(&g_sumsq, (double)s2); }
    }
    if (threadIdx.x == 0){
        __threadfence();
        unsigned t = atomicAdd(&g_ticket, 1u);
        last = (t == (unsigned)(gridDim.x - 1));
    }
    __syncthreads();
    if (last && threadIdx.x == 0){
        double S = g_sum, S2 = g_sumsq;
        double mean = S / (double)E;
        double var  = (S2 - S*S/(double)E) / (double)(E - 1);
        g_mean = (float)mean;
        g_istd = (float)(1.0 / sqrt(var));
        g_ticket = 0u;
        g_sum = 0.0; g_sumsq = 0.0;
    }
}

// ---------------- K1: histogram of node occurrences (both sides) ----------------
__global__ void k_hist(const int* __restrict__ ei32, int E){
    int is64 = g_is64;
    for (int e = blockIdx.x*blockDim.x + threadIdx.x; e < E; e += gridDim.x*blockDim.x){
        int s, tg;
        if (is64){ s = ei32[2*(size_t)e]; tg = ei32[2*((size_t)E + e)]; }
        else     { s = ei32[e];           tg = ei32[E + e]; }
        atomicAdd(&g_hist[tg], 1);
        atomicAdd(&g_hist[s],  1);
    }
}

// ---------------- K2: exclusive scan of hist -> cursor (single block) ----------------
__global__ __launch_bounds__(1024) void k_scan(){
    __shared__ int wsum[32];
    int t = threadIdx.x, lane = t & 31, w = t >> 5;
    int carry = 0;
    const int NCH = (NN + 1023)/1024;
    for (int ch = 0; ch < NCH; ch++){
        int i = ch*1024 + t;
        int v = (i < NN) ? g_hist[i] : 0;
        int x = v;
        #pragma unroll
        for (int o = 1; o < 32; o <<= 1){
            int y = __shfl_up_sync(0xffffffffu, x, o);
            if (lane >= o) x += y;
        }
        if (lane == 31) wsum[w] = x;
        __syncthreads();
        if (w == 0){
            int sv = wsum[lane];
            #pragma unroll
            for (int o = 1; o < 32; o <<= 1){
                int y = __shfl_up_sync(0xffffffffu, sv, o);
                if (lane >= o) sv += y;
            }
            wsum[lane] = sv;
        }
        __syncthreads();
        int incl = x + (w > 0 ? wsum[w-1] : 0);
        int total = wsum[31];
        if (i < NN) g_cur[i] = carry + incl - v;
        carry += total;
        __syncthreads();
    }
}

// ---------------- K3: scatter half-edges into sorted order ----------------
__global__ void k_scatter(const int* __restrict__ ei32, int E){
    int is64 = g_is64;
    for (int e = blockIdx.x*blockDim.x + threadIdx.x; e < E; e += gridDim.x*blockDim.x){
        int s, tg;
        if (is64){ s = ei32[2*(size_t)e]; tg = ei32[2*((size_t)E + e)]; }
        else     { s = ei32[e];           tg = ei32[E + e]; }
        int p1 = atomicAdd(&g_cur[tg], 1);           // + side at tgt
        g_arrA[p1] = (unsigned)e;
        g_arrB[p1] = (unsigned)tg | ((unsigned)s << 16);
        int p2 = atomicAdd(&g_cur[s], 1);            // - side at src
        g_arrA[p2] = (unsigned)e | 0x80000000u;
        g_arrB[p2] = (unsigned)s | ((unsigned)tg << 16);
    }
}

// ---------------- KB: per-node projections, split halves, smem-staged I/O ----------------
__global__ __launch_bounds__(PB) void k_proj(
    const float* __restrict__ x, const float* __restrict__ W1,
    const float* __restrict__ b1)
{
    __shared__ float4 st[PB*9];
    __shared__ __align__(16) float sW[32*32];
    __shared__ __align__(16) float sb[32];
    int half = blockIdx.y;
    int tid = threadIdx.x;
    for (int k = tid; k < 32*32; k += PB) sW[k] = W1[half*32*32 + k];
    if (tid < 32) sb[tid] = half ? b1[tid] : 0.f;

    int base = blockIdx.x*PB;
    const float4* x4 = (const float4*)x;
    #pragma unroll
    for (int k = tid; k < PB*8; k += PB){
        int row = k >> 3, q = k & 7;
        int gr = base + row;
        if (gr < BN) st[row*9 + q] = x4[(size_t)gr*8 + q];
    }
    __syncthreads();

    F4U2 xr[8];
    #pragma unroll
    for (int q = 0; q < 8; q++) xr[q].f4 = st[tid*9 + q];

    __align__(16) ull acc[16];
    const float4* sb4 = (const float4*)sb;
    #pragma unroll
    for (int q = 0; q < 8; q++){
        F4U2 b; b.f4 = sb4[q];
        acc[2*q] = b.u[0]; acc[2*q+1] = b.u[1];
    }
    #pragma unroll
    for (int i = 0; i < 32; i++){
        float v = xr[i >> 2].f[i & 3];
        ull vv = pack2(v, v);
        const float4* wr = (const float4*)(sW + i*32);
        #pragma unroll
        for (int q = 0; q < 8; q++){
            F4U2 w; w.f4 = wr[q];
            FMA2(acc[2*q],   vv, w.u[0]);
            FMA2(acc[2*q+1], vv, w.u[1]);
        }
    }
    __syncthreads();
    const float4* aa = (const float4*)acc;
    #pragma unroll
    for (int q = 0; q < 8; q++) st[tid*9 + q] = aa[q];
    __syncthreads();
    float4* y4 = (float4*)(half ? g_YB : g_YA);
    #pragma unroll
    for (int k = tid; k < PB*8; k += PB){
        int row = k >> 3, q = k & 7;
        int gr = base + row;
        if (gr < BN) y4[(size_t)gr*8 + q] = st[row*9 + q];
    }
}

// ---------------- KD: sorted half-edge MLP + segmented reduce + sparse atomics ----------------
__global__ __launch_bounds__(BD) void k_gather(const float* __restrict__ eattr,
                                               const float* __restrict__ W1,
                                               const float* __restrict__ W2,
                                               const float* __restrict__ b2,
                                               int twoE)
{
    __shared__ float4 sA[BD*9];               // gather stage A; later reused as sH
    __shared__ float4 sB[BD*9];
    __shared__ __align__(16) float sW2[32*32];
    __shared__ __align__(16) float sw1c[32];
    __shared__ __align__(16) float sb2[32];
    __shared__ int sIA[BD], sIB[BD];
    __shared__ unsigned short sNode[BD];
    __shared__ short sSeg[BD + 1];
    __shared__ int wHead[BD/32];

    int t = threadIdx.x;
    int b = blockIdx.y;
    for (int k = t; k < 32*32; k += BD){
        int i = k >> 5, j = k & 31;
        sW2[k] = (j < H2) ? W2[i*H2 + j] : 0.f;
    }
    if (t < 32){
        sw1c[t] = W1[64*32 + t];
        sb2[t]  = (t < H2) ? b2[t] : 0.f;
    }

    int i = blockIdx.x*BD + t;
    bool act = i < twoE;
    unsigned es = act ? g_arrA[i] : 0u;
    unsigned nb = act ? g_arrB[i] : 0u;
    int node  = (int)(nb & 0xFFFFu);
    int other = (int)(nb >> 16);
    int e   = (int)(es & 0x7FFFFFFFu);
    int neg = (int)(es >> 31);
    float ea = act ? (eattr[e] - g_mean) * g_istd : 0.f;
    int srcN = neg ? node  : other;
    int tgtN = neg ? other : node;
    sIA[t] = b*NN + srcN;
    sIB[t] = b*NN + tgtN;
    sNode[t] = act ? (unsigned short)node : (unsigned short)0xFFFFu;
    __syncthreads();

    // Coalesced gather: 8 consecutive threads fetch one 128B row.
    const float4* ya4 = (const float4*)g_YA;
    const float4* yb4 = (const float4*)g_YB;
    #pragma unroll
    for (int k = t; k < BD*8; k += BD){
        int row = k >> 3, q = k & 7;
        sA[row*9 + q] = ya4[(size_t)sIA[row]*8 + q];
        sB[row*9 + q] = yb4[(size_t)sIB[row]*8 + q];
    }
    __syncthreads();

    // Layer 1: h1 = sigm(YA[src] + YB[tgt] + ea*w1c)
    float h1[32];
    ull eaea = pack2(ea, ea);
    const float4* w1c4 = (const float4*)sw1c;
    #pragma unroll
    for (int q = 0; q < 8; q++){
        F4U2 a; a.f4 = sA[t*9 + q];
        F4U2 tt; tt.f4 = sB[t*9 + q];
        F4U2 w; w.f4 = w1c4[q];
        ull s0, s1;
        ADD2(s0, a.u[0], tt.u[0]);
        ADD2(s1, a.u[1], tt.u[1]);
        FMA2(s0, eaea, w.u[0]);
        FMA2(s1, eaea, w.u[1]);
        F4U2 r; r.u[0] = s0; r.u[1] = s1;
        h1[4*q+0] = sigm_fast(r.f[0]);
        h1[4*q+1] = sigm_fast(r.f[1]);
        h1[4*q+2] = sigm_fast(r.f[2]);
        h1[4*q+3] = sigm_fast(r.f[3]);
    }

    // Layer 2: 30 cols, f32x2 accumulators
    __align__(16) ull acc[15];
    const float4* sb24 = (const float4*)sb2;
    #pragma unroll
    for (int q = 0; q < 7; q++){
        F4U2 bb; bb.f4 = sb24[q];
        acc[2*q] = bb.u[0]; acc[2*q+1] = bb.u[1];
    }
    { F2U1 bt; bt.f2 = *(const float2*)(sb2 + 28); acc[14] = bt.u; }
    #pragma unroll
    for (int k = 0; k < 32; k++){
        float hv = h1[k];
        ull hh = pack2(hv, hv);
        const float4* wr = (const float4*)(sW2 + k*32);
        #pragma unroll
        for (int q = 0; q < 7; q++){
            F4U2 w; w.f4 = wr[q];
            FMA2(acc[2*q],   hh, w.u[0]);
            FMA2(acc[2*q+1], hh, w.u[1]);
        }
        F2U1 wt; wt.f2 = *(const float2*)(sW2 + k*32 + 28);
        FMA2(acc[14], hh, wt.u);
    }
    float sgn = neg ? -1.f : 1.f;
    if (!act) sgn = 0.f;
    float h2[30];
    #pragma unroll
    for (int p = 0; p < 15; p++){
        F2U1 r; r.u = acc[p];
        h2[2*p+0] = sgn * sigm_fast(r.f[0]);
        h2[2*p+1] = sgn * sigm_fast(r.f[1]);
    }

    // Stage signed h2 into smem (reuse sA), stride-33 rows (conflict-free column walks)
    __syncthreads();
    float* sH = (float*)sA;
    #pragma unroll
    for (int p = 0; p < 30; p++) sH[t*33 + p] = h2[p];

    // Segment heads by node id
    int head = (t == 0) || (sNode[t] != sNode[t-1]);
    unsigned bal = __ballot_sync(0xffffffffu, head);
    int lane = t & 31, w = t >> 5;
    if (lane == 0) wHead[w] = __popc(bal);
    __syncthreads();
    int basecnt = 0;
    #pragma unroll
    for (int k = 0; k < BD/32; k++) if (k < w) basecnt += wHead[k];
    int nseg = 0;
    #pragma unroll
    for (int k = 0; k < BD/32; k++) nseg += wHead[k];
    if (head){
        int s = basecnt + __popc(bal & ((1u << lane) - 1u));
        sSeg[s] = (short)t;
    }
    __syncthreads();
    if (t == 0) sSeg[nseg] = (short)BD;
    __syncthreads();

    // Reduce each segment, one warp-group per segment round-robin, lane=column
    int g = t >> 5, c = t & 31;
    for (int s = g; s < nseg; s += BD/32){
        int r0 = sSeg[s], r1 = sSeg[s+1];
        int nd = sNode[r0];
        if (c < H2 && nd != 0xFFFF){
            float sum = 0.f;
            for (int r = r0; r < r1; r++) sum += sH[r*33 + c];
            red_add_f(g_SC + ((size_t)(b*NN + nd))*32 + c, sum);
        }
    }
}

// ---------------- KE: out = sigmoid(SC @ W3 + b3), split 16-col halves, staged I/O ----------------
__global__ __launch_bounds__(PB) void k_out(
    float* __restrict__ out, const float* __restrict__ W3,
    const float* __restrict__ b3)
{
    __shared__ float4 st[PB*9];
    __shared__ __align__(16) float sW[30*16];
    __shared__ __align__(16) float sb[16];
    int half = blockIdx.y;
    int tid = threadIdx.x;
    for (int k = tid; k < 30*16; k += PB){
        int r = k >> 4, c = k & 15;
        sW[k] = W3[r*32 + half*16 + c];
    }
    if (tid < 16) sb[tid] = b3[half*16 + tid];

    int base = blockIdx.x*PB;
    const float4* sc4 = (const float4*)g_SC;
    #pragma unroll
    for (int k = tid; k < PB*8; k += PB){
        int row = k >> 3, q = k & 7;
        int gr = base + row;
        if (gr < BN) st[row*9 + q] = sc4[(size_t)gr*8 + q];
    }
    __syncthreads();

    F4U2 sr[8];
    #pragma unroll
    for (int q = 0; q < 8; q++) sr[q].f4 = st[tid*9 + q];

    __align__(16) ull acc[8];
    const float4* sb4 = (const float4*)sb;
    #pragma unroll
    for (int q = 0; q < 4; q++){
        F4U2 bb; bb.f4 = sb4[q];
        acc[2*q] = bb.u[0]; acc[2*q+1] = bb.u[1];
    }
    #pragma unroll
    for (int k = 0; k < 30; k++){
        float sv = sr[k >> 2].f[k & 3];
        ull vv = pack2(sv, sv);
        const float4* wr = (const float4*)(sW + k*16);
        #pragma unroll
        for (int q = 0; q < 4; q++){
            F4U2 w; w.f4 = wr[q];
            FMA2(acc[2*q],   vv, w.u[0]);
            FMA2(acc[2*q+1], vv, w.u[1]);
        }
    }
    __align__(16) float res[16];
    #pragma unroll
    for (int q = 0; q < 4; q++){
        F4U2 r; r.u[0] = acc[2*q]; r.u[1] = acc[2*q+1];
        res[4*q+0] = sigmoidf(r.f[0]);
        res[4*q+1] = sigmoidf(r.f[1]);
        res[4*q+2] = sigmoidf(r.f[2]);
        res[4*q+3] = sigmoidf(r.f[3]);
    }

    __syncthreads();
    float4* st5 = (float4*)st;
    const float4* rr = (const float4*)res;
    #pragma unroll
    for (int q = 0; q < 4; q++) st5[tid*5 + q] = rr[q];
    __syncthreads();
    float4* o4 = (float4*)out;
    #pragma unroll
    for (int k = tid; k < PB*4; k += PB){
        int row = k >> 2, q = k & 3;
        int gr = base + row;
        if (gr < BN) o4[(size_t)gr*8 + half*4 + q] = st5[row*5 + q];
    }
}

extern "C" void kernel_launch(void* const* d_in, const int* in_sizes, int n_in,
                              void* d_out, int out_size){
    const float* x     = (const float*)d_in[0];
    const int*   ei32  = (const int*)d_in[1];
    const float* eattr = (const float*)d_in[2];
    const float* W1    = (const float*)d_in[3];
    const float* b1    = (const float*)d_in[4];
    const float* W2    = (const float*)d_in[5];
    const float* b2    = (const float*)d_in[6];
    const float* W3    = (const float*)d_in[7];
    const float* b3    = (const float*)d_in[8];
    int E = in_sizes[1] / 2;
    int twoE = 2*E;

    k_init<<<IG, 256>>>(ei32, eattr, E);
    k_hist<<<512, 256>>>(ei32, E);
    k_scan<<<1, 1024>>>();
    k_scatter<<<512, 256>>>(ei32, E);
    dim3 pg((BN + PB - 1)/PB, 2);
    k_proj<<<pg, PB>>>(x, W1, b1);
    dim3 gg((twoE + BD - 1)/BD, NB);
    k_gather<<<gg, BD>>>(eattr, W1, W2, b2, twoE);
    k_out<<<pg, PB>>>((float*)d_out, W3, b3);
}

// round 9
// speedup vs baseline: 1.8496x; 1.8496x over previous
#include <cuda_runtime.h>

#define NB   4
#define NN   50000
#define FIN  32
#define H2   30
#define BN   (NB*NN)       // 200000 node-batch rows
#define BD   128           // edge-kernel block size
#define PB   256           // proj/out block size
#define IG   1024          // init grid

typedef unsigned long long ull;

// Static scratch (no allocations allowed).
__device__ __align__(128) float g_YA[(size_t)BN*32];   // x @ W1[0:32]
__device__ __align__(128) float g_YB[(size_t)BN*32];   // x @ W1[32:64] + b1
__device__ __align__(128) float g_SC[(size_t)BN*32];   // padded 30->32 accumulator
__device__ double g_sum, g_sumsq;
__device__ float  g_mean, g_istd;
__device__ int    g_is64;
__device__ unsigned g_ticket;

union F4U2 { float4 f4; ull u[2]; float f[4]; };
union F2U1 { float2 f2; ull u; float f[2]; };

__device__ __forceinline__ float sigmoidf(float x){          // final layer
    return __fdividef(1.0f, 1.0f + __expf(-x));
}
__device__ __forceinline__ float sigm_fast(float x){         // hidden layers
    float t;
    asm("tanh.approx.f32 %0, %1;" : "=f"(t) : "f"(x * 0.5f));
    return fmaf(t, 0.5f, 0.5f);
}
__device__ __forceinline__ ull pack2(float lo, float hi){
    ull r; asm("mov.b64 %0, {%1,%2};" : "=l"(r) : "f"(lo), "f"(hi)); return r;
}
#define FMA2(acc, a, b) asm("fma.rn.f32x2 %0, %1, %2, %0;" : "+l"(acc) : "l"(a), "l"(b))
#define ADD2(d, a, b)   asm("add.rn.f32x2 %0, %1, %2;"     : "=l"(d)  : "l"(a), "l"(b))

__device__ __forceinline__ void red_add_v4(float* p, float a, float b, float c, float d){
    asm volatile("red.global.add.v4.f32 [%0], {%1,%2,%3,%4};"
                 :: "l"(p), "f"(a), "f"(b), "f"(c), "f"(d) : "memory");
}
__device__ __forceinline__ void red_add_v2(float* p, float a, float b){
    asm volatile("red.global.add.v2.f32 [%0], {%1,%2};"
                 :: "l"(p), "f"(a), "f"(b) : "memory");
}

// ---------------- K0: zero SC + edge_attr stats + probe + finalize (fused) ----------------
__global__ void k_init(const int* __restrict__ ei32, const float* __restrict__ ea, int E){
    size_t n4 = (size_t)BN*32/4;
    float4 z = make_float4(0.f,0.f,0.f,0.f);
    float4* p = (float4*)g_SC;
    for (size_t i = (size_t)blockIdx.x*blockDim.x + threadIdx.x; i < n4;
         i += (size_t)gridDim.x*blockDim.x) p[i] = z;

    if (blockIdx.x==0 && threadIdx.x==0){
        int all_hi_zero = 1;
        for (int k = 1; k < 512; k += 2) all_hi_zero &= (ei32[k] == 0);
        g_is64 = all_hi_zero;
    }

    float s = 0.f, s2 = 0.f;
    for (int i = blockIdx.x*blockDim.x + threadIdx.x; i < E; i += gridDim.x*blockDim.x){
        float v = ea[i]; s += v; s2 = fmaf(v, v, s2);
    }
    #pragma unroll
    for (int o = 16; o; o >>= 1){
        s  += __shfl_down_sync(0xffffffffu, s,  o);
        s2 += __shfl_down_sync(0xffffffffu, s2, o);
    }
    __shared__ float ws[32], ws2[32];
    __shared__ int last;
    int lane = threadIdx.x & 31, w = threadIdx.x >> 5;
    if (lane == 0){ ws[w] = s; ws2[w] = s2; }
    __syncthreads();
    if (w == 0){
        int nw = blockDim.x >> 5;
        s  = (lane < nw) ? ws[lane]  : 0.f;
        s2 = (lane < nw) ? ws2[lane] : 0.f;
        #pragma unroll
        for (int o = 16; o; o >>= 1){
            s  += __shfl_down_sync(0xffffffffu, s,  o);
            s2 += __shfl_down_sync(0xffffffffu, s2, o);
        }
        if (lane == 0){ atomicAdd(&g_sum, (double)s); atomicAdd(&g_sumsq, (double)s2); }
    }
    if (threadIdx.x == 0){
        __threadfence();
        unsigned t = atomicAdd(&g_ticket, 1u);
        last = (t == (unsigned)(gridDim.x - 1));
    }
    __syncthreads();
    if (last && threadIdx.x == 0){
        double S = g_sum, S2 = g_sumsq;
        double mean = S / (double)E;
        double var  = (S2 - S*S/(double)E) / (double)(E - 1);
        g_mean = (float)mean;
        g_istd = (float)(1.0 / sqrt(var));
        g_ticket = 0u;
        g_sum = 0.0; g_sumsq = 0.0;
    }
}

// ---------------- KB: per-node projections, split halves, smem-staged I/O ----------------
__global__ __launch_bounds__(PB) void k_proj(
    const float* __restrict__ x, const float* __restrict__ W1,
    const float* __restrict__ b1)
{
    __shared__ float4 st[PB*9];
    __shared__ __align__(16) float sW[32*32];
    __shared__ __align__(16) float sb[32];
    int half = blockIdx.y;
    int tid = threadIdx.x;
    for (int k = tid; k < 32*32; k += PB) sW[k] = W1[half*32*32 + k];
    if (tid < 32) sb[tid] = half ? b1[tid] : 0.f;

    int base = blockIdx.x*PB;
    const float4* x4 = (const float4*)x;
    #pragma unroll
    for (int k = tid; k < PB*8; k += PB){
        int row = k >> 3, q = k & 7;
        int gr = base + row;
        if (gr < BN) st[row*9 + q] = x4[(size_t)gr*8 + q];
    }
    __syncthreads();

    F4U2 xr[8];
    #pragma unroll
    for (int q = 0; q < 8; q++) xr[q].f4 = st[tid*9 + q];

    __align__(16) ull acc[16];
    const float4* sb4 = (const float4*)sb;
    #pragma unroll
    for (int q = 0; q < 8; q++){
        F4U2 b; b.f4 = sb4[q];
        acc[2*q] = b.u[0]; acc[2*q+1] = b.u[1];
    }
    #pragma unroll
    for (int i = 0; i < 32; i++){
        float v = xr[i >> 2].f[i & 3];
        ull vv = pack2(v, v);
        const float4* wr = (const float4*)(sW + i*32);
        #pragma unroll
        for (int q = 0; q < 8; q++){
            F4U2 w; w.f4 = wr[q];
            FMA2(acc[2*q],   vv, w.u[0]);
            FMA2(acc[2*q+1], vv, w.u[1]);
        }
    }
    __syncthreads();
    const float4* aa = (const float4*)acc;
    #pragma unroll
    for (int q = 0; q < 8; q++) st[tid*9 + q] = aa[q];
    __syncthreads();
    float4* y4 = (float4*)(half ? g_YB : g_YA);
    #pragma unroll
    for (int k = tid; k < PB*8; k += PB){
        int row = k >> 3, q = k & 7;
        int gr = base + row;
        if (gr < BN) y4[(size_t)gr*8 + q] = st[row*9 + q];
    }
}

// ---------------- KD: edge MLP, warp-local gather, ONE block barrier ----------------
__global__ __launch_bounds__(BD) void k_edge(
    const int* __restrict__ ei32, const float* __restrict__ eattr,
    const float* __restrict__ W1, const float* __restrict__ W2,
    const float* __restrict__ b2, int E)
{
    __shared__ float4 sA[BD*9];               // stride 9 float4: conflict-free
    __shared__ float4 sB[BD*9];
    __shared__ __align__(16) float sW2[32*32];  // 32 rows, stride 32, cols 0..29 used
    __shared__ __align__(16) float sw1c[32];
    __shared__ __align__(16) float sb2[32];

    int tid = threadIdx.x;
    int lane = tid & 31, w = tid >> 5;

    for (int k = tid; k < 32*32; k += BD){
        int i = k >> 5, j = k & 31;
        sW2[k] = (j < H2) ? W2[i*H2 + j] : 0.f;
    }
    if (tid < 32){
        sw1c[tid] = W1[64*32 + tid];
        sb2[tid]  = (tid < H2) ? b2[tid] : 0.f;
    }
    __syncthreads();                          // ONLY block barrier (weights visible)

    long long item  = (long long)blockIdx.x*BD + tid;
    bool active = item < 4LL*E;
    int e = active ? (int)(item >> 2) : 0;
    int b = (int)(item & 3);
    int is64 = g_is64;
    int src, tgt;
    if (is64){ src = ei32[2*(size_t)e]; tgt = ei32[2*((size_t)E + e)]; }
    else     { src = ei32[e];           tgt = ei32[E + e]; }
    float ea = active ? (eattr[e] - g_mean) * g_istd : 0.f;
    int ia = b*NN + src;                      // subtract side
    int ib = b*NN + tgt;                      // add side

    // Warp-local coalesced gather: this warp stages its own 32 items' rows.
    // Row indices distributed by shfl; 8 consecutive lanes fetch one 128B row.
    const float4* ya4 = (const float4*)g_YA;
    const float4* yb4 = (const float4*)g_YB;
    int rowbase = w*32;
    int q = lane & 7;
    #pragma unroll
    for (int it = 0; it < 8; it++){
        int iw = 4*it + (lane >> 3);          // item-in-warp 0..31
        int iaW = __shfl_sync(0xffffffffu, ia, iw);
        int ibW = __shfl_sync(0xffffffffu, ib, iw);
        int R = rowbase + iw;
        sA[R*9 + q] = ya4[(size_t)iaW*8 + q];
        sB[R*9 + q] = yb4[(size_t)ibW*8 + q];
    }
    __syncwarp();                             // warp-local staging only

    // Layer 1: h1 = sigm(YA[src] + YB[tgt] + ea*w1c)
    float h1[32];
    ull eaea = pack2(ea, ea);
    const float4* w1c4 = (const float4*)sw1c;
    #pragma unroll
    for (int p = 0; p < 8; p++){
        F4U2 a; a.f4 = sA[tid*9 + p];
        F4U2 t; t.f4 = sB[tid*9 + p];
        F4U2 wv; wv.f4 = w1c4[p];
        ull s0, s1;
        ADD2(s0, a.u[0], t.u[0]);
        ADD2(s1, a.u[1], t.u[1]);
        FMA2(s0, eaea, wv.u[0]);
        FMA2(s1, eaea, wv.u[1]);
        F4U2 r; r.u[0] = s0; r.u[1] = s1;
        h1[4*p+0] = sigm_fast(r.f[0]);
        h1[4*p+1] = sigm_fast(r.f[1]);
        h1[4*p+2] = sigm_fast(r.f[2]);
        h1[4*p+3] = sigm_fast(r.f[3]);
    }

    // Layer 2: 30 columns (7 float4 + 1 float2 per row), f32x2 accumulators
    __align__(16) ull acc[15];
    const float4* sb24 = (const float4*)sb2;
    #pragma unroll
    for (int p = 0; p < 7; p++){
        F4U2 bb; bb.f4 = sb24[p];
        acc[2*p] = bb.u[0]; acc[2*p+1] = bb.u[1];
    }
    { F2U1 bt; bt.f2 = *(const float2*)(sb2 + 28); acc[14] = bt.u; }
    #pragma unroll
    for (int i = 0; i < 32; i++){
        float hv = h1[i];
        ull hh = pack2(hv, hv);
        const float4* wr = (const float4*)(sW2 + i*32);
        #pragma unroll
        for (int p = 0; p < 7; p++){
            F4U2 wv; wv.f4 = wr[p];
            FMA2(acc[2*p],   hh, wv.u[0]);
            FMA2(acc[2*p+1], hh, wv.u[1]);
        }
        F2U1 wt; wt.f2 = *(const float2*)(sW2 + i*32 + 28);
        FMA2(acc[14], hh, wt.u);
    }
    float h2[30];
    #pragma unroll
    for (int p = 0; p < 15; p++){
        F2U1 r; r.u = acc[p];
        h2[2*p+0] = sigm_fast(r.f[0]);
        h2[2*p+1] = sigm_fast(r.f[1]);
    }

    if (active){
        float* pt = g_SC + (size_t)ib*32;
        float* ps = g_SC + (size_t)ia*32;
        #pragma unroll
        for (int p = 0; p < 7; p++){
            red_add_v4(pt + 4*p,  h2[4*p],  h2[4*p+1],  h2[4*p+2],  h2[4*p+3]);
            red_add_v4(ps + 4*p, -h2[4*p], -h2[4*p+1], -h2[4*p+2], -h2[4*p+3]);
        }
        red_add_v2(pt + 28,  h2[28],  h2[29]);
        red_add_v2(ps + 28, -h2[28], -h2[29]);
    }
}

// ---------------- KE: out = sigmoid(SC @ W3 + b3), split 16-col halves, staged I/O ----------------
__global__ __launch_bounds__(PB) void k_out(
    float* __restrict__ out, const float* __restrict__ W3,
    const float* __restrict__ b3)
{
    __shared__ float4 st[PB*9];
    __shared__ __align__(16) float sW[30*16];
    __shared__ __align__(16) float sb[16];
    int half = blockIdx.y;
    int tid = threadIdx.x;
    for (int k = tid; k < 30*16; k += PB){
        int r = k >> 4, c = k & 15;
        sW[k] = W3[r*32 + half*16 + c];
    }
    if (tid < 16) sb[tid] = b3[half*16 + tid];

    int base = blockIdx.x*PB;
    const float4* sc4 = (const float4*)g_SC;
    #pragma unroll
    for (int k = tid; k < PB*8; k += PB){
        int row = k >> 3, q = k & 7;
        int gr = base + row;
        if (gr < BN) st[row*9 + q] = sc4[(size_t)gr*8 + q];
    }
    __syncthreads();

    F4U2 sr[8];
    #pragma unroll
    for (int q = 0; q < 8; q++) sr[q].f4 = st[tid*9 + q];

    __align__(16) ull acc[8];
    const float4* sb4 = (const float4*)sb;
    #pragma unroll
    for (int q = 0; q < 4; q++){
        F4U2 bb; bb.f4 = sb4[q];
        acc[2*q] = bb.u[0]; acc[2*q+1] = bb.u[1];
    }
    #pragma unroll
    for (int k = 0; k < 30; k++){
        float sv = sr[k >> 2].f[k & 3];
        ull vv = pack2(sv, sv);
        const float4* wr = (const float4*)(sW + k*16);
        #pragma unroll
        for (int q = 0; q < 4; q++){
            F4U2 w; w.f4 = wr[q];
            FMA2(acc[2*q],   vv, w.u[0]);
            FMA2(acc[2*q+1], vv, w.u[1]);
        }
    }
    __align__(16) float res[16];
    #pragma unroll
    for (int q = 0; q < 4; q++){
        F4U2 r; r.u[0] = acc[2*q]; r.u[1] = acc[2*q+1];
        res[4*q+0] = sigmoidf(r.f[0]);
        res[4*q+1] = sigmoidf(r.f[1]);
        res[4*q+2] = sigmoidf(r.f[2]);
        res[4*q+3] = sigmoidf(r.f[3]);
    }

    __syncthreads();
    float4* st5 = (float4*)st;
    const float4* rr = (const float4*)res;
    #pragma unroll
    for (int q = 0; q < 4; q++) st5[tid*5 + q] = rr[q];
    __syncthreads();
    float4* o4 = (float4*)out;
    #pragma unroll
    for (int k = tid; k < PB*4; k += PB){
        int row = k >> 2, q = k & 3;
        int gr = base + row;
        if (gr < BN) o4[(size_t)gr*8 + half*4 + q] = st5[row*5 + q];
    }
}

extern "C" void kernel_launch(void* const* d_in, const int* in_sizes, int n_in,
                              void* d_out, int out_size){
    const float* x     = (const float*)d_in[0];
    const int*   ei32  = (const int*)d_in[1];
    const float* eattr = (const float*)d_in[2];
    const float* W1    = (const float*)d_in[3];
    const float* b1    = (const float*)d_in[4];
    const float* W2    = (const float*)d_in[5];
    const float* b2    = (const float*)d_in[6];
    const float* W3    = (const float*)d_in[7];
    const float* b3    = (const float*)d_in[8];
    int E = in_sizes[1] / 2;

    k_init<<<IG, 256>>>(ei32, eattr, E);
    dim3 pg((BN + PB - 1)/PB, 2);
    k_proj<<<pg, PB>>>(x, W1, b1);
    long long items = 4LL * E;
    int blocks = (int)((items + BD - 1) / BD);
    k_edge<<<blocks, BD>>>(ei32, eattr, W1, W2, b2, E);
    k_out<<<pg, PB>>>((float*)d_out, W3, b3);
}

// round 10
// speedup vs baseline: 1.9727x; 1.0666x over previous
#include <cuda_runtime.h>

#define NB   4
#define NN   50000
#define FIN  32
#define H2   30
#define BN   (NB*NN)       // 200000 node-batch rows
#define BD   128           // edge-kernel block size
#define PB   256           // proj/out block size
#define IG   1024          // init grid

typedef unsigned long long ull;

// Static scratch (no allocations allowed).
__device__ __align__(128) float g_YA[(size_t)BN*32];   // x @ W1[0:32]
__device__ __align__(128) float g_YB[(size_t)BN*32];   // x @ W1[32:64] + b1
__device__ __align__(128) float g_SC[(size_t)BN*32];   // padded 30->32 accumulator
__device__ double g_sum, g_sumsq;
__device__ float  g_mean, g_istd;
__device__ int    g_is64;
__device__ unsigned g_ticket;

union F4U2 { float4 f4; ull u[2]; float f[4]; };
union F2U1 { float2 f2; ull u; float f[2]; };

__device__ __forceinline__ float sigmoidf(float x){          // final layer
    return __fdividef(1.0f, 1.0f + __expf(-x));
}
__device__ __forceinline__ float sigm_fast(float x){         // hidden layers
    float t;
    asm("tanh.approx.f32 %0, %1;" : "=f"(t) : "f"(x * 0.5f));
    return fmaf(t, 0.5f, 0.5f);
}
__device__ __forceinline__ ull pack2(float lo, float hi){
    ull r; asm("mov.b64 %0, {%1,%2};" : "=l"(r) : "f"(lo), "f"(hi)); return r;
}
#define FMA2(acc, a, b) asm("fma.rn.f32x2 %0, %1, %2, %0;" : "+l"(acc) : "l"(a), "l"(b))
#define ADD2(d, a, b)   asm("add.rn.f32x2 %0, %1, %2;"     : "=l"(d)  : "l"(a), "l"(b))

__device__ __forceinline__ void red_add_v4(float* p, float a, float b, float c, float d){
    asm volatile("red.global.add.v4.f32 [%0], {%1,%2,%3,%4};"
                 :: "l"(p), "f"(a), "f"(b), "f"(c), "f"(d) : "memory");
}
__device__ __forceinline__ void red_add_v2(float* p, float a, float b){
    asm volatile("red.global.add.v2.f32 [%0], {%1,%2};"
                 :: "l"(p), "f"(a), "f"(b) : "memory");
}

// ---------------- K0: zero SC + edge_attr stats + probe + finalize (fused) ----------------
__global__ void k_init(const int* __restrict__ ei32, const float* __restrict__ ea, int E){
    size_t n4 = (size_t)BN*32/4;
    float4 z = make_float4(0.f,0.f,0.f,0.f);
    float4* p = (float4*)g_SC;
    for (size_t i = (size_t)blockIdx.x*blockDim.x + threadIdx.x; i < n4;
         i += (size_t)gridDim.x*blockDim.x) p[i] = z;

    if (blockIdx.x==0 && threadIdx.x==0){
        int all_hi_zero = 1;
        for (int k = 1; k < 512; k += 2) all_hi_zero &= (ei32[k] == 0);
        g_is64 = all_hi_zero;
    }

    float s = 0.f, s2 = 0.f;
    for (int i = blockIdx.x*blockDim.x + threadIdx.x; i < E; i += gridDim.x*blockDim.x){
        float v = ea[i]; s += v; s2 = fmaf(v, v, s2);
    }
    #pragma unroll
    for (int o = 16; o; o >>= 1){
        s  += __shfl_down_sync(0xffffffffu, s,  o);
        s2 += __shfl_down_sync(0xffffffffu, s2, o);
    }
    __shared__ float ws[32], ws2[32];
    __shared__ int last;
    int lane = threadIdx.x & 31, w = threadIdx.x >> 5;
    if (lane == 0){ ws[w] = s; ws2[w] = s2; }
    __syncthreads();
    if (w == 0){
        int nw = blockDim.x >> 5;
        s  = (lane < nw) ? ws[lane]  : 0.f;
        s2 = (lane < nw) ? ws2[lane] : 0.f;
        #pragma unroll
        for (int o = 16; o; o >>= 1){
            s  += __shfl_down_sync(0xffffffffu, s,  o);
            s2 += __shfl_down_sync(0xffffffffu, s2, o);
        }
        if (lane == 0){ atomicAdd(&g_sum, (double)s); atomicAdd(&g_sumsq, (double)s2); }
    }
    if (threadIdx.x == 0){
        __threadfence();
        unsigned t = atomicAdd(&g_ticket, 1u);
        last = (t == (unsigned)(gridDim.x - 1));
    }
    __syncthreads();
    if (last && threadIdx.x == 0){
        double S = g_sum, S2 = g_sumsq;
        double mean = S / (double)E;
        double var  = (S2 - S*S/(double)E) / (double)(E - 1);
        g_mean = (float)mean;
        g_istd = (float)(1.0 / sqrt(var));
        g_ticket = 0u;
        g_sum = 0.0; g_sumsq = 0.0;
    }
}

// ---------------- KB: per-node projections, split halves, smem-staged I/O ----------------
__global__ __launch_bounds__(PB) void k_proj(
    const float* __restrict__ x, const float* __restrict__ W1,
    const float* __restrict__ b1)
{
    __shared__ float4 st[PB*9];
    __shared__ __align__(16) float sW[32*32];
    __shared__ __align__(16) float sb[32];
    int half = blockIdx.y;
    int tid = threadIdx.x;
    for (int k = tid; k < 32*32; k += PB) sW[k] = W1[half*32*32 + k];
    if (tid < 32) sb[tid] = half ? b1[tid] : 0.f;

    int base = blockIdx.x*PB;
    const float4* x4 = (const float4*)x;
    #pragma unroll
    for (int k = tid; k < PB*8; k += PB){
        int row = k >> 3, q = k & 7;
        int gr = base + row;
        if (gr < BN) st[row*9 + q] = x4[(size_t)gr*8 + q];
    }
    __syncthreads();

    F4U2 xr[8];
    #pragma unroll
    for (int q = 0; q < 8; q++) xr[q].f4 = st[tid*9 + q];

    __align__(16) ull acc[16];
    const float4* sb4 = (const float4*)sb;
    #pragma unroll
    for (int q = 0; q < 8; q++){
        F4U2 b; b.f4 = sb4[q];
        acc[2*q] = b.u[0]; acc[2*q+1] = b.u[1];
    }
    #pragma unroll
    for (int i = 0; i < 32; i++){
        float v = xr[i >> 2].f[i & 3];
        ull vv = pack2(v, v);
        const float4* wr = (const float4*)(sW + i*32);
        #pragma unroll
        for (int q = 0; q < 8; q++){
            F4U2 w; w.f4 = wr[q];
            FMA2(acc[2*q],   vv, w.u[0]);
            FMA2(acc[2*q+1], vv, w.u[1]);
        }
    }
    __syncthreads();
    const float4* aa = (const float4*)acc;
    #pragma unroll
    for (int q = 0; q < 8; q++) st[tid*9 + q] = aa[q];
    __syncthreads();
    float4* y4 = (float4*)(half ? g_YB : g_YA);
    #pragma unroll
    for (int k = tid; k < PB*8; k += PB){
        int row = k >> 3, q = k & 7;
        int gr = base + row;
        if (gr < BN) y4[(size_t)gr*8 + q] = st[row*9 + q];
    }
}

// ---------------- KD: edge MLP, fused gather-add, warp-local, one barrier ----------------
__global__ __launch_bounds__(BD) void k_edge(
    const int* __restrict__ ei32, const float* __restrict__ eattr,
    const float* __restrict__ W1, const float* __restrict__ W2,
    const float* __restrict__ b2, int E)
{
    __shared__ float4 sS[BD*9];                 // staged YA[src]+YB[tgt], stride 9
    __shared__ __align__(16) float sW2[32*32];  // 32 rows, stride 32, cols 0..29 used
    __shared__ __align__(16) float sw1c[32];
    __shared__ __align__(16) float sb2[32];

    int tid = threadIdx.x;
    int lane = tid & 31, w = tid >> 5;

    for (int k = tid; k < 32*32; k += BD){
        int i = k >> 5, j = k & 31;
        sW2[k] = (j < H2) ? W2[i*H2 + j] : 0.f;
    }
    if (tid < 32){
        sw1c[tid] = W1[64*32 + tid];
        sb2[tid]  = (tid < H2) ? b2[tid] : 0.f;
    }
    __syncthreads();                          // ONLY block barrier (weights visible)

    long long item  = (long long)blockIdx.x*BD + tid;
    bool active = item < 4LL*E;
    int e = active ? (int)(item >> 2) : 0;
    int b = (int)(item & 3);
    int is64 = g_is64;
    int src, tgt;
    if (is64){ src = ei32[2*(size_t)e]; tgt = ei32[2*((size_t)E + e)]; }
    else     { src = ei32[e];           tgt = ei32[E + e]; }
    float ea = active ? (eattr[e] - g_mean) * g_istd : 0.f;
    int ia = b*NN + src;                      // subtract side
    int ib = b*NN + tgt;                      // add side

    // Warp-local coalesced gather with fused add: 8 lanes service one item row;
    // each lane loads YA[src] and YB[tgt] quarters and stores their SUM.
    const float4* ya4 = (const float4*)g_YA;
    const float4* yb4 = (const float4*)g_YB;
    int rowbase = w*32;
    int q = lane & 7;
    #pragma unroll
    for (int it = 0; it < 8; it++){
        int iw = 4*it + (lane >> 3);          // item-in-warp 0..31
        int iaW = __shfl_sync(0xffffffffu, ia, iw);
        int ibW = __shfl_sync(0xffffffffu, ib, iw);
        int R = rowbase + iw;
        float4 va = ya4[(size_t)iaW*8 + q];
        float4 vb = yb4[(size_t)ibW*8 + q];
        float4 vs;
        vs.x = va.x + vb.x; vs.y = va.y + vb.y;
        vs.z = va.z + vb.z; vs.w = va.w + vb.w;
        sS[R*9 + q] = vs;
    }
    __syncwarp();                             // warp-local staging only

    // Layer 1: h1 = sigm(sum + ea*w1c)
    float h1[32];
    ull eaea = pack2(ea, ea);
    const float4* w1c4 = (const float4*)sw1c;
    #pragma unroll
    for (int p = 0; p < 8; p++){
        F4U2 a; a.f4 = sS[tid*9 + p];
        F4U2 wv; wv.f4 = w1c4[p];
        ull s0 = a.u[0], s1 = a.u[1];
        FMA2(s0, eaea, wv.u[0]);
        FMA2(s1, eaea, wv.u[1]);
        F4U2 r; r.u[0] = s0; r.u[1] = s1;
        h1[4*p+0] = sigm_fast(r.f[0]);
        h1[4*p+1] = sigm_fast(r.f[1]);
        h1[4*p+2] = sigm_fast(r.f[2]);
        h1[4*p+3] = sigm_fast(r.f[3]);
    }

    // Layer 2: 30 columns (7 float4 + 1 float2 per row), f32x2 accumulators
    __align__(16) ull acc[15];
    const float4* sb24 = (const float4*)sb2;
    #pragma unroll
    for (int p = 0; p < 7; p++){
        F4U2 bb; bb.f4 = sb24[p];
        acc[2*p] = bb.u[0]; acc[2*p+1] = bb.u[1];
    }
    { F2U1 bt; bt.f2 = *(const float2*)(sb2 + 28); acc[14] = bt.u; }
    #pragma unroll
    for (int i = 0; i < 32; i++){
        float hv = h1[i];
        ull hh = pack2(hv, hv);
        const float4* wr = (const float4*)(sW2 + i*32);
        #pragma unroll
        for (int p = 0; p < 7; p++){
            F4U2 wv; wv.f4 = wr[p];
            FMA2(acc[2*p],   hh, wv.u[0]);
            FMA2(acc[2*p+1], hh, wv.u[1]);
        }
        F2U1 wt; wt.f2 = *(const float2*)(sW2 + i*32 + 28);
        FMA2(acc[14], hh, wt.u);
    }
    float h2[30];
    #pragma unroll
    for (int p = 0; p < 15; p++){
        F2U1 r; r.u = acc[p];
        h2[2*p+0] = sigm_fast(r.f[0]);
        h2[2*p+1] = sigm_fast(r.f[1]);
    }

    if (active){
        float* pt = g_SC + (size_t)ib*32;
        float* ps = g_SC + (size_t)ia*32;
        #pragma unroll
        for (int p = 0; p < 7; p++){
            red_add_v4(pt + 4*p,  h2[4*p],  h2[4*p+1],  h2[4*p+2],  h2[4*p+3]);
            red_add_v4(ps + 4*p, -h2[4*p], -h2[4*p+1], -h2[4*p+2], -h2[4*p+3]);
        }
        red_add_v2(pt + 28,  h2[28],  h2[29]);
        red_add_v2(ps + 28, -h2[28], -h2[29]);
    }
}

// ---------------- KE: out = sigmoid(SC @ W3 + b3), split 16-col halves, staged I/O ----------------
__global__ __launch_bounds__(PB) void k_out(
    float* __restrict__ out, const float* __restrict__ W3,
    const float* __restrict__ b3)
{
    __shared__ float4 st[PB*9];
    __shared__ __align__(16) float sW[30*16];
    __shared__ __align__(16) float sb[16];
    int half = blockIdx.y;
    int tid = threadIdx.x;
    for (int k = tid; k < 30*16; k += PB){
        int r = k >> 4, c = k & 15;
        sW[k] = W3[r*32 + half*16 + c];
    }
    if (tid < 16) sb[tid] = b3[half*16 + tid];

    int base = blockIdx.x*PB;
    const float4* sc4 = (const float4*)g_SC;
    #pragma unroll
    for (int k = tid; k < PB*8; k += PB){
        int row = k >> 3, q = k & 7;
        int gr = base + row;
        if (gr < BN) st[row*9 + q] = sc4[(size_t)gr*8 + q];
    }
    __syncthreads();

    F4U2 sr[8];
    #pragma unroll
    for (int q = 0; q < 8; q++) sr[q].f4 = st[tid*9 + q];

    __align__(16) ull acc[8];
    const float4* sb4 = (const float4*)sb;
    #pragma unroll
    for (int q = 0; q < 4; q++){
        F4U2 bb; bb.f4 = sb4[q];
        acc[2*q] = bb.u[0]; acc[2*q+1] = bb.u[1];
    }
    #pragma unroll
    for (int k = 0; k < 30; k++){
        float sv = sr[k >> 2].f[k & 3];
        ull vv = pack2(sv, sv);
        const float4* wr = (const float4*)(sW + k*16);
        #pragma unroll
        for (int q = 0; q < 4; q++){
            F4U2 w; w.f4 = wr[q];
            FMA2(acc[2*q],   vv, w.u[0]);
            FMA2(acc[2*q+1], vv, w.u[1]);
        }
    }
    __align__(16) float res[16];
    #pragma unroll
    for (int q = 0; q < 4; q++){
        F4U2 r; r.u[0] = acc[2*q]; r.u[1] = acc[2*q+1];
        res[4*q+0] = sigmoidf(r.f[0]);
        res[4*q+1] = sigmoidf(r.f[1]);
        res[4*q+2] = sigmoidf(r.f[2]);
        res[4*q+3] = sigmoidf(r.f[3]);
    }

    __syncthreads();
    float4* st5 = (float4*)st;
    const float4* rr = (const float4*)res;
    #pragma unroll
    for (int q = 0; q < 4; q++) st5[tid*5 + q] = rr[q];
    __syncthreads();
    float4* o4 = (float4*)out;
    #pragma unroll
    for (int k = tid; k < PB*4; k += PB){
        int row = k >> 2, q = k & 3;
        int gr = base + row;
        if (gr < BN) o4[(size_t)gr*8 + half*4 + q] = st5[row*5 + q];
    }
}

extern "C" void kernel_launch(void* const* d_in, const int* in_sizes, int n_in,
                              void* d_out, int out_size){
    const float* x     = (const float*)d_in[0];
    const int*   ei32  = (const int*)d_in[1];
    const float* eattr = (const float*)d_in[2];
    const float* W1    = (const float*)d_in[3];
    const float* b1    = (const float*)d_in[4];
    const float* W2    = (const float*)d_in[5];
    const float* b2    = (const float*)d_in[6];
    const float* W3    = (const float*)d_in[7];
    const float* b3    = (const float*)d_in[8];
    int E = in_sizes[1] / 2;

    k_init<<<IG, 256>>>(ei32, eattr, E);
    dim3 pg((BN + PB - 1)/PB, 2);
    k_proj<<<pg, PB>>>(x, W1, b1);
    long long items = 4LL * E;
    int blocks = (int)((items + BD - 1) / BD);
    k_edge<<<blocks, BD>>>(ei32, eattr, W1, W2, b2, E);
    k_out<<<pg, PB>>>((float*)d_out, W3, b3);
}

// round 11
// speedup vs baseline: 1.9823x; 1.0049x over previous
#include <cuda_runtime.h>

#define NB   4
#define NN   50000
#define FIN  32
#define H2   30
#define BN   (NB*NN)       // 200000 node-batch rows
#define BD   128           // edge-kernel block size
#define PB   256           // proj/out block size
#define IG   1024          // init grid

typedef unsigned long long ull;

// Static scratch (no allocations allowed).
__device__ __align__(128) float g_YA[(size_t)BN*32];   // x @ W1[0:32]
__device__ __align__(128) float g_YB[(size_t)BN*32];   // x @ W1[32:64] + b1
__device__ __align__(128) float g_SC[(size_t)BN*32];   // padded 30->32 accumulator
__device__ double g_sum, g_sumsq;
__device__ float  g_mean, g_istd;
__device__ int    g_is64;
__device__ unsigned g_ticket;

union F4U2 { float4 f4; ull u[2]; float f[4]; };
union F2U1 { float2 f2; ull u; float f[2]; };

__device__ __forceinline__ float sigmoidf(float x){          // final layer
    return __fdividef(1.0f, 1.0f + __expf(-x));
}
__device__ __forceinline__ float sigm_fast(float x){         // hidden layers
    float t;
    asm("tanh.approx.f32 %0, %1;" : "=f"(t) : "f"(x * 0.5f));
    return fmaf(t, 0.5f, 0.5f);
}
__device__ __forceinline__ ull pack2(float lo, float hi){
    ull r; asm("mov.b64 %0, {%1,%2};" : "=l"(r) : "f"(lo), "f"(hi)); return r;
}
#define FMA2(acc, a, b) asm("fma.rn.f32x2 %0, %1, %2, %0;" : "+l"(acc) : "l"(a), "l"(b))
#define ADD2(d, a, b)   asm("add.rn.f32x2 %0, %1, %2;"     : "=l"(d)  : "l"(a), "l"(b))

__device__ __forceinline__ void red_add_v4(float* p, float a, float b, float c, float d){
    asm volatile("red.global.add.v4.f32 [%0], {%1,%2,%3,%4};"
                 :: "l"(p), "f"(a), "f"(b), "f"(c), "f"(d) : "memory");
}
__device__ __forceinline__ void red_add_v2(float* p, float a, float b){
    asm volatile("red.global.add.v2.f32 [%0], {%1,%2};"
                 :: "l"(p), "f"(a), "f"(b) : "memory");
}

// ---------------- K0: zero SC + edge_attr stats + probe + finalize (fused) ----------------
__global__ void k_init(const int* __restrict__ ei32, const float* __restrict__ ea, int E){
    size_t n4 = (size_t)BN*32/4;
    float4 z = make_float4(0.f,0.f,0.f,0.f);
    float4* p = (float4*)g_SC;
    for (size_t i = (size_t)blockIdx.x*blockDim.x + threadIdx.x; i < n4;
         i += (size_t)gridDim.x*blockDim.x) p[i] = z;

    if (blockIdx.x==0 && threadIdx.x==0){
        int all_hi_zero = 1;
        for (int k = 1; k < 512; k += 2) all_hi_zero &= (ei32[k] == 0);
        g_is64 = all_hi_zero;
    }

    float s = 0.f, s2 = 0.f;
    for (int i = blockIdx.x*blockDim.x + threadIdx.x; i < E; i += gridDim.x*blockDim.x){
        float v = ea[i]; s += v; s2 = fmaf(v, v, s2);
    }
    #pragma unroll
    for (int o = 16; o; o >>= 1){
        s  += __shfl_down_sync(0xffffffffu, s,  o);
        s2 += __shfl_down_sync(0xffffffffu, s2, o);
    }
    __shared__ float ws[32], ws2[32];
    __shared__ int last;
    int lane = threadIdx.x & 31, w = threadIdx.x >> 5;
    if (lane == 0){ ws[w] = s; ws2[w] = s2; }
    __syncthreads();
    if (w == 0){
        int nw = blockDim.x >> 5;
        s  = (lane < nw) ? ws[lane]  : 0.f;
        s2 = (lane < nw) ? ws2[lane] : 0.f;
        #pragma unroll
        for (int o = 16; o; o >>= 1){
            s  += __shfl_down_sync(0xffffffffu, s,  o);
            s2 += __shfl_down_sync(0xffffffffu, s2, o);
        }
        if (lane == 0){ atomicAdd(&g_sum, (double)s); atomicAdd(&g_sumsq, (double)s2); }
    }
    if (threadIdx.x == 0){
        __threadfence();
        unsigned t = atomicAdd(&g_ticket, 1u);
        last = (t == (unsigned)(gridDim.x - 1));
    }
    __syncthreads();
    if (last && threadIdx.x == 0){
        double S = g_sum, S2 = g_sumsq;
        double mean = S / (double)E;
        double var  = (S2 - S*S/(double)E) / (double)(E - 1);
        g_mean = (float)mean;
        g_istd = (float)(1.0 / sqrt(var));
        g_ticket = 0u;
        g_sum = 0.0; g_sumsq = 0.0;
    }
}

// ---------------- KB: per-node projections, split halves, smem-staged I/O ----------------
__global__ __launch_bounds__(PB) void k_proj(
    const float* __restrict__ x, const float* __restrict__ W1,
    const float* __restrict__ b1)
{
    __shared__ float4 st[PB*9];
    __shared__ __align__(16) float sW[32*32];
    __shared__ __align__(16) float sb[32];
    int half = blockIdx.y;
    int tid = threadIdx.x;
    for (int k = tid; k < 32*32; k += PB) sW[k] = W1[half*32*32 + k];
    if (tid < 32) sb[tid] = half ? b1[tid] : 0.f;

    int base = blockIdx.x*PB;
    const float4* x4 = (const float4*)x;
    #pragma unroll
    for (int k = tid; k < PB*8; k += PB){
        int row = k >> 3, q = k & 7;
        int gr = base + row;
        if (gr < BN) st[row*9 + q] = x4[(size_t)gr*8 + q];
    }
    __syncthreads();

    F4U2 xr[8];
    #pragma unroll
    for (int q = 0; q < 8; q++) xr[q].f4 = st[tid*9 + q];

    __align__(16) ull acc[16];
    const float4* sb4 = (const float4*)sb;
    #pragma unroll
    for (int q = 0; q < 8; q++){
        F4U2 b; b.f4 = sb4[q];
        acc[2*q] = b.u[0]; acc[2*q+1] = b.u[1];
    }
    #pragma unroll
    for (int i = 0; i < 32; i++){
        float v = xr[i >> 2].f[i & 3];
        ull vv = pack2(v, v);
        const float4* wr = (const float4*)(sW + i*32);
        #pragma unroll
        for (int q = 0; q < 8; q++){
            F4U2 w; w.f4 = wr[q];
            FMA2(acc[2*q],   vv, w.u[0]);
            FMA2(acc[2*q+1], vv, w.u[1]);
        }
    }
    __syncthreads();
    const float4* aa = (const float4*)acc;
    #pragma unroll
    for (int q = 0; q < 8; q++) st[tid*9 + q] = aa[q];
    __syncthreads();
    float4* y4 = (float4*)(half ? g_YB : g_YA);
    #pragma unroll
    for (int k = tid; k < PB*8; k += PB){
        int row = k >> 3, q = k & 7;
        int gr = base + row;
        if (gr < BN) y4[(size_t)gr*8 + q] = st[row*9 + q];
    }
}

// ---------------- KD: edge MLP, fused gather-add, interleaved layers (low regs) ----------------
__global__ __launch_bounds__(BD) void k_edge(
    const int* __restrict__ ei32, const float* __restrict__ eattr,
    const float* __restrict__ W1, const float* __restrict__ W2,
    const float* __restrict__ b2, int E)
{
    __shared__ float4 sS[BD*9];                 // staged YA[src]+YB[tgt], stride 9
    __shared__ __align__(16) float sW2[32*32];  // 32 rows, stride 32, cols 0..29 used
    __shared__ __align__(16) float sw1c[32];
    __shared__ __align__(16) float sb2[32];

    int tid = threadIdx.x;
    int lane = tid & 31, w = tid >> 5;

    for (int k = tid; k < 32*32; k += BD){
        int i = k >> 5, j = k & 31;
        sW2[k] = (j < H2) ? W2[i*H2 + j] : 0.f;
    }
    if (tid < 32){
        sw1c[tid] = W1[64*32 + tid];
        sb2[tid]  = (tid < H2) ? b2[tid] : 0.f;
    }
    __syncthreads();                          // ONLY block barrier (weights visible)

    long long item  = (long long)blockIdx.x*BD + tid;
    bool active = item < 4LL*E;
    int e = active ? (int)(item >> 2) : 0;
    int b = (int)(item & 3);
    int is64 = g_is64;
    int src, tgt;
    if (is64){ src = ei32[2*(size_t)e]; tgt = ei32[2*((size_t)E + e)]; }
    else     { src = ei32[e];           tgt = ei32[E + e]; }
    float ea = active ? (eattr[e] - g_mean) * g_istd : 0.f;
    int ia = b*NN + src;                      // subtract side
    int ib = b*NN + tgt;                      // add side

    // Warp-local coalesced gather with fused add: 8 lanes service one item row.
    const float4* ya4 = (const float4*)g_YA;
    const float4* yb4 = (const float4*)g_YB;
    int rowbase = w*32;
    int q = lane & 7;
    #pragma unroll
    for (int it = 0; it < 8; it++){
        int iw = 4*it + (lane >> 3);          // item-in-warp 0..31
        int iaW = __shfl_sync(0xffffffffu, ia, iw);
        int ibW = __shfl_sync(0xffffffffu, ib, iw);
        int R = rowbase + iw;
        float4 va = ya4[(size_t)iaW*8 + q];
        float4 vb = yb4[(size_t)ibW*8 + q];
        float4 vs;
        vs.x = va.x + vb.x; vs.y = va.y + vb.y;
        vs.z = va.z + vb.z; vs.w = va.w + vb.w;
        sS[R*9 + q] = vs;
    }
    __syncwarp();                             // warp-local staging only

    // Interleaved layer1 + layer2: compute 4 h1 values, consume them
    // immediately into the 30-wide layer-2 accumulators, discard.
    __align__(16) ull acc[15];
    const float4* sb24 = (const float4*)sb2;
    #pragma unroll
    for (int p = 0; p < 7; p++){
        F4U2 bb; bb.f4 = sb24[p];
        acc[2*p] = bb.u[0]; acc[2*p+1] = bb.u[1];
    }
    { F2U1 bt; bt.f2 = *(const float2*)(sb2 + 28); acc[14] = bt.u; }

    ull eaea = pack2(ea, ea);
    const float4* w1c4 = (const float4*)sw1c;
    #pragma unroll
    for (int p = 0; p < 8; p++){
        F4U2 a; a.f4 = sS[tid*9 + p];
        F4U2 wv; wv.f4 = w1c4[p];
        ull s0 = a.u[0], s1 = a.u[1];
        FMA2(s0, eaea, wv.u[0]);
        FMA2(s1, eaea, wv.u[1]);
        F4U2 r; r.u[0] = s0; r.u[1] = s1;
        float h0 = sigm_fast(r.f[0]);
        float h1v = sigm_fast(r.f[1]);
        float h2v = sigm_fast(r.f[2]);
        float h3v = sigm_fast(r.f[3]);
        #pragma unroll
        for (int c = 0; c < 4; c++){
            float hv = (c == 0) ? h0 : (c == 1) ? h1v : (c == 2) ? h2v : h3v;
            ull hh = pack2(hv, hv);
            const float4* wr = (const float4*)(sW2 + (4*p + c)*32);
            #pragma unroll
            for (int m = 0; m < 7; m++){
                F4U2 w2v; w2v.f4 = wr[m];
                FMA2(acc[2*m],   hh, w2v.u[0]);
                FMA2(acc[2*m+1], hh, w2v.u[1]);
            }
            F2U1 wt; wt.f2 = *(const float2*)(sW2 + (4*p + c)*32 + 28);
            FMA2(acc[14], hh, wt.u);
        }
    }
    float h2[30];
    #pragma unroll
    for (int p = 0; p < 15; p++){
        F2U1 r; r.u = acc[p];
        h2[2*p+0] = sigm_fast(r.f[0]);
        h2[2*p+1] = sigm_fast(r.f[1]);
    }

    if (active){
        float* pt = g_SC + (size_t)ib*32;
        float* ps = g_SC + (size_t)ia*32;
        #pragma unroll
        for (int p = 0; p < 7; p++){
            red_add_v4(pt + 4*p,  h2[4*p],  h2[4*p+1],  h2[4*p+2],  h2[4*p+3]);
            red_add_v4(ps + 4*p, -h2[4*p], -h2[4*p+1], -h2[4*p+2], -h2[4*p+3]);
        }
        red_add_v2(pt + 28,  h2[28],  h2[29]);
        red_add_v2(ps + 28, -h2[28], -h2[29]);
    }
}

// ---------------- KE: out = sigmoid(SC @ W3 + b3), split 16-col halves, staged I/O ----------------
__global__ __launch_bounds__(PB) void k_out(
    float* __restrict__ out, const float* __restrict__ W3,
    const float* __restrict__ b3)
{
    __shared__ float4 st[PB*9];
    __shared__ __align__(16) float sW[30*16];
    __shared__ __align__(16) float sb[16];
    int half = blockIdx.y;
    int tid = threadIdx.x;
    for (int k = tid; k < 30*16; k += PB){
        int r = k >> 4, c = k & 15;
        sW[k] = W3[r*32 + half*16 + c];
    }
    if (tid < 16) sb[tid] = b3[half*16 + tid];

    int base = blockIdx.x*PB;
    const float4* sc4 = (const float4*)g_SC;
    #pragma unroll
    for (int k = tid; k < PB*8; k += PB){
        int row = k >> 3, q = k & 7;
        int gr = base + row;
        if (gr < BN) st[row*9 + q] = sc4[(size_t)gr*8 + q];
    }
    __syncthreads();

    F4U2 sr[8];
    #pragma unroll
    for (int q = 0; q < 8; q++) sr[q].f4 = st[tid*9 + q];

    __align__(16) ull acc[8];
    const float4* sb4 = (const float4*)sb;
    #pragma unroll
    for (int q = 0; q < 4; q++){
        F4U2 bb; bb.f4 = sb4[q];
        acc[2*q] = bb.u[0]; acc[2*q+1] = bb.u[1];
    }
    #pragma unroll
    for (int k = 0; k < 30; k++){
        float sv = sr[k >> 2].f[k & 3];
        ull vv = pack2(sv, sv);
        const float4* wr = (const float4*)(sW + k*16);
        #pragma unroll
        for (int q = 0; q < 4; q++){
            F4U2 w; w.f4 = wr[q];
            FMA2(acc[2*q],   vv, w.u[0]);
            FMA2(acc[2*q+1], vv, w.u[1]);
        }
    }
    __align__(16) float res[16];
    #pragma unroll
    for (int q = 0; q < 4; q++){
        F4U2 r; r.u[0] = acc[2*q]; r.u[1] = acc[2*q+1];
        res[4*q+0] = sigmoidf(r.f[0]);
        res[4*q+1] = sigmoidf(r.f[1]);
        res[4*q+2] = sigmoidf(r.f[2]);
        res[4*q+3] = sigmoidf(r.f[3]);
    }

    __syncthreads();
    float4* st5 = (float4*)st;
    const float4* rr = (const float4*)res;
    #pragma unroll
    for (int q = 0; q < 4; q++) st5[tid*5 + q] = rr[q];
    __syncthreads();
    float4* o4 = (float4*)out;
    #pragma unroll
    for (int k = tid; k < PB*4; k += PB){
        int row = k >> 2, q = k & 3;
        int gr = base + row;
        if (gr < BN) o4[(size_t)gr*8 + half*4 + q] = st5[row*5 + q];
    }
}

extern "C" void kernel_launch(void* const* d_in, const int* in_sizes, int n_in,
                              void* d_out, int out_size){
    const float* x     = (const float*)d_in[0];
    const int*   ei32  = (const int*)d_in[1];
    const float* eattr = (const float*)d_in[2];
    const float* W1    = (const float*)d_in[3];
    const float* b1    = (const float*)d_in[4];
    const float* W2    = (const float*)d_in[5];
    const float* b2    = (const float*)d_in[6];
    const float* W3    = (const float*)d_in[7];
    const float* b3    = (const float*)d_in[8];
    int E = in_sizes[1] / 2;

    k_init<<<IG, 256>>>(ei32, eattr, E);
    dim3 pg((BN + PB - 1)/PB, 2);
    k_proj<<<pg, PB>>>(x, W1, b1);
    long long items = 4LL * E;
    int blocks = (int)((items + BD - 1) / BD);
    k_edge<<<blocks, BD>>>(ei32, eattr, W1, W2, b2, E);
    k_out<<<pg, PB>>>((float*)d_out, W3, b3);
}